// round 1
// baseline (speedup 1.0000x reference)
#include <cuda_runtime.h>
#include <math.h>

#define B_ 8192
#define D_ 256
#define H_ 266
#define T_ 20
#define NMAX 288
#define RC 32
#define EPS 1e-5f

#define BM 64
#define BN 64
#define BK 16

// ---------------- scratch (no allocation allowed) ----------------
__device__ float g_x[B_ * D_];
__device__ float g_v[B_];
__device__ float g_h1[B_ * H_];
__device__ float g_h2[B_ * H_];
__device__ float g_grad[B_ * D_];
__device__ float g_psum[RC * NMAX];
__device__ float g_psq[RC * NMAX];
__device__ float g_scale[NMAX];
__device__ float g_shift[NMAX];

// ---------------- GEMM: Y[B,N] = act(A)[B,K] @ W[N,K]^T + bias[N] ----------------
// act(A) = AFFINE ? relu(A*scale[k]+shift[k]) : A   (per input-feature column k)
template <bool AFFINE>
__global__ void gemm_kernel(const float* __restrict__ A,
                            const float* __restrict__ W,
                            const float* __restrict__ bias,
                            const float* __restrict__ scale,
                            const float* __restrict__ shift,
                            float* __restrict__ Y, int K, int N) {
    __shared__ float As[BK][BM];
    __shared__ float Ws[BK][BN + 4];  // pad to soften bank conflicts

    const int m0 = blockIdx.x * BM;
    const int n0 = blockIdx.y * BN;
    const int tid = threadIdx.x;          // 256 threads
    const int tx = tid & 15;              // 0..15 -> 4 cols each
    const int ty = tid >> 4;              // 0..15 -> 4 rows each

    float acc[4][4] = {};

    const int ktiles = (K + BK - 1) / BK;
    for (int kt = 0; kt < ktiles; kt++) {
        const int k0 = kt * BK;
        // load A tile (64 x 16), apply fused BN-affine + relu
#pragma unroll
        for (int l = 0; l < 4; l++) {
            int idx = tid + l * 256;
            int mi = idx >> 4;      // /BK
            int ki = idx & 15;      // %BK
            int kg = k0 + ki;
            float a = 0.f;
            if (kg < K) {
                a = A[(size_t)(m0 + mi) * K + kg];
                if (AFFINE) a = fmaxf(fmaf(a, scale[kg], shift[kg]), 0.f);
            }
            As[ki][mi] = a;
        }
        // load W tile (64 x 16)
#pragma unroll
        for (int l = 0; l < 4; l++) {
            int idx = tid + l * 256;
            int ni = idx >> 4;
            int ki = idx & 15;
            int kg = k0 + ki;
            int ng = n0 + ni;
            float w = 0.f;
            if (kg < K && ng < N) w = W[(size_t)ng * K + kg];
            Ws[ki][ni] = w;
        }
        __syncthreads();
#pragma unroll
        for (int k = 0; k < BK; k++) {
            float ra[4], rb[4];
#pragma unroll
            for (int i = 0; i < 4; i++) ra[i] = As[k][ty * 4 + i];
#pragma unroll
            for (int j = 0; j < 4; j++) rb[j] = Ws[k][tx * 4 + j];
#pragma unroll
            for (int i = 0; i < 4; i++)
#pragma unroll
                for (int j = 0; j < 4; j++)
                    acc[i][j] = fmaf(ra[i], rb[j], acc[i][j]);
        }
        __syncthreads();
    }

#pragma unroll
    for (int i = 0; i < 4; i++) {
        int mg = m0 + ty * 4 + i;  // B divisible by BM -> always valid
#pragma unroll
        for (int j = 0; j < 4; j++) {
            int ng = n0 + tx * 4 + j;
            if (ng < N) Y[(size_t)mg * N + ng] = acc[i][j] + bias[ng];
        }
    }
}

// ---------------- column stats: per-chunk partial sums (deterministic, no atomics) ----------------
__global__ void colstats_kernel(const float* __restrict__ Y, int N,
                                float* __restrict__ psum, float* __restrict__ psq) {
    // grid: (ceil(N/32), RC); block 256 = 32 cols x 8 rows
    const int lane = threadIdx.x & 31;
    const int yrow = threadIdx.x >> 5;  // 0..7
    const int col = blockIdx.x * 32 + lane;
    const int chunk = blockIdx.y;
    const int rows_per_chunk = B_ / RC;  // 256
    const int r0 = chunk * rows_per_chunk;

    float s = 0.f, q = 0.f;
    if (col < N) {
        for (int r = r0 + yrow; r < r0 + rows_per_chunk; r += 8) {
            float v = Y[(size_t)r * N + col];
            s += v;
            q = fmaf(v, v, q);
        }
    }
    __shared__ float ss[8][32], sq[8][32];
    ss[yrow][lane] = s;
    sq[yrow][lane] = q;
    __syncthreads();
    if (yrow == 0) {
#pragma unroll
        for (int y = 1; y < 8; y++) { s += ss[y][lane]; q += sq[y][lane]; }
        if (col < N) {
            psum[chunk * NMAX + col] = s;
            psq[chunk * NMAX + col] = q;
        }
    }
}

__global__ void finalize_kernel(const float* __restrict__ g, const float* __restrict__ be,
                                int N, const float* __restrict__ psum,
                                const float* __restrict__ psq,
                                float* __restrict__ scale, float* __restrict__ shift) {
    int n = blockIdx.x * blockDim.x + threadIdx.x;
    if (n >= N) return;
    float s = 0.f, q = 0.f;
    for (int c = 0; c < RC; c++) { s += psum[c * NMAX + n]; q += psq[c * NMAX + n]; }
    float m = s * (1.f / B_);
    float var = q * (1.f / B_) - m * m;
    float inv = rsqrtf(var + EPS);
    float sc = g[n] * inv;
    scale[n] = sc;
    shift[n] = be[n] - m * sc;
}

// ---------------- per-row SDE update ----------------
__global__ void update_kernel(const float* __restrict__ grad, const float* __restrict__ xi_t,
                              const float* __restrict__ tg, int t,
                              float* __restrict__ x, float* __restrict__ v) {
    const int row = blockIdx.x;
    const int d = threadIdx.x;  // 256 == D_
    const float ht = tg[t + 1] - tg[t];
    const float sh = sqrtf(ht);
    const size_t idx = (size_t)row * D_ + d;
    const float g = grad[idx];
    const float noise = sh * xi_t[idx];  // sigma = 1
    float f = g * g;
    float dt = g * noise;
#pragma unroll
    for (int o = 16; o > 0; o >>= 1) {
        f += __shfl_down_sync(0xFFFFFFFFu, f, o);
        dt += __shfl_down_sync(0xFFFFFFFFu, dt, o);
    }
    __shared__ float sf[8], sd[8];
    const int w = d >> 5;
    if ((d & 31) == 0) { sf[w] = f; sd[w] = dt; }
    __syncthreads();
    if (d == 0) {
        float F = 0.f, DT = 0.f;
#pragma unroll
        for (int i = 0; i < 8; i++) { F += sf[i]; DT += sd[i]; }
        v[row] += -F * ht + DT;  // v - f*h + dot
    }
    x[idx] += -g * ht + noise;  // alpha = -grad (lambda=1)
}

// ---------------- small helpers ----------------
__global__ void copy_kernel(const float* __restrict__ src, float* __restrict__ dst, int n) {
    int i = blockIdx.x * blockDim.x + threadIdx.x;
    if (i < n) dst[i] = src[i];
}

__global__ void v0_finish_kernel(const float* __restrict__ yv, const float* __restrict__ scale,
                                 const float* __restrict__ shift, float* __restrict__ v) {
    int i = blockIdx.x * blockDim.x + threadIdx.x;
    if (i < B_) v[i] = fmaxf(fmaf(yv[i], scale[0], shift[0]), 0.f);
}

__global__ void writeout_kernel(const float* __restrict__ v, const float* __restrict__ x,
                                float* __restrict__ out) {
    int i = blockIdx.x * blockDim.x + threadIdx.x;
    if (i < B_) out[i] = v[i];
    if (i < B_ * D_) out[B_ + i] = x[i];
}

// ---------------- host orchestration ----------------
static float* sym(const void* s) {
    void* p = nullptr;
    cudaGetSymbolAddress(&p, s);
    return (float*)p;
}

static void launch_gemm(const float* A, bool affine, const float* W, const float* bias,
                        int K, int N, float* Y, const float* scale, const float* shift) {
    dim3 grid(B_ / BM, (N + BN - 1) / BN);
    if (affine)
        gemm_kernel<true><<<grid, 256>>>(A, W, bias, scale, shift, Y, K, N);
    else
        gemm_kernel<false><<<grid, 256>>>(A, W, bias, scale, shift, Y, K, N);
}

static void launch_stats(const float* Y, int N, const float* g, const float* be,
                         float* psum, float* psq, float* scale, float* shift) {
    dim3 grid((N + 31) / 32, RC);
    colstats_kernel<<<grid, 256>>>(Y, N, psum, psq);
    finalize_kernel<<<(N + 255) / 256, 256>>>(g, be, N, psum, psq, scale, shift);
}

extern "C" void kernel_launch(void* const* d_in, const int* in_sizes, int n_in,
                              void* d_out, int out_size) {
    const float* x    = (const float*)d_in[0];
    const float* xi   = (const float*)d_in[1];
    const float* tg   = (const float*)d_in[2];
    const float* W1   = (const float*)d_in[3];
    const float* b1   = (const float*)d_in[4];
    const float* g1   = (const float*)d_in[5];
    const float* be1  = (const float*)d_in[6];
    const float* W2   = (const float*)d_in[7];
    const float* b2   = (const float*)d_in[8];
    const float* g2   = (const float*)d_in[9];
    const float* be2  = (const float*)d_in[10];
    const float* W3   = (const float*)d_in[11];
    const float* b3   = (const float*)d_in[12];
    const float* vW1  = (const float*)d_in[13];
    const float* vb1  = (const float*)d_in[14];
    const float* vg1  = (const float*)d_in[15];
    const float* vbe1 = (const float*)d_in[16];
    const float* vW2  = (const float*)d_in[17];
    const float* vb2  = (const float*)d_in[18];
    const float* vg2  = (const float*)d_in[19];
    const float* vbe2 = (const float*)d_in[20];
    const float* vW3  = (const float*)d_in[21];
    const float* vb3  = (const float*)d_in[22];
    const float* vg3  = (const float*)d_in[23];
    const float* vbe3 = (const float*)d_in[24];

    float* xbuf  = sym(g_x);
    float* vbuf  = sym(g_v);
    float* h1    = sym(g_h1);
    float* h2    = sym(g_h2);
    float* grad  = sym(g_grad);
    float* psum  = sym(g_psum);
    float* psq   = sym(g_psq);
    float* scale = sym(g_scale);
    float* shift = sym(g_shift);

    // init x state
    copy_kernel<<<(B_ * D_ + 255) / 256, 256>>>(x, xbuf, B_ * D_);

    // ---- v0 network on the initial x ----
    launch_gemm(x, false, vW1, vb1, D_, H_, h1, nullptr, nullptr);
    launch_stats(h1, H_, vg1, vbe1, psum, psq, scale, shift);
    launch_gemm(h1, true, vW2, vb2, H_, H_, h2, scale, shift);
    launch_stats(h2, H_, vg2, vbe2, psum, psq, scale, shift);
    launch_gemm(h2, true, vW3, vb3, H_, 1, grad, scale, shift);  // yv in grad buffer [B,1]
    launch_stats(grad, 1, vg3, vbe3, psum, psq, scale, shift);
    v0_finish_kernel<<<(B_ + 255) / 256, 256>>>(grad, scale, shift, vbuf);

    // ---- time-stepping scan ----
    for (int t = 0; t < T_; t++) {
        const float* W1t = W1 + (size_t)t * H_ * D_;
        const float* b1t = b1 + (size_t)t * H_;
        const float* g1t = g1 + (size_t)t * H_;
        const float* be1t = be1 + (size_t)t * H_;
        const float* W2t = W2 + (size_t)t * H_ * H_;
        const float* b2t = b2 + (size_t)t * H_;
        const float* g2t = g2 + (size_t)t * H_;
        const float* be2t = be2 + (size_t)t * H_;
        const float* W3t = W3 + (size_t)t * D_ * H_;
        const float* b3t = b3 + (size_t)t * D_;
        const float* xit = xi + (size_t)t * B_ * D_;

        launch_gemm(xbuf, false, W1t, b1t, D_, H_, h1, nullptr, nullptr);
        launch_stats(h1, H_, g1t, be1t, psum, psq, scale, shift);
        launch_gemm(h1, true, W2t, b2t, H_, H_, h2, scale, shift);
        launch_stats(h2, H_, g2t, be2t, psum, psq, scale, shift);
        launch_gemm(h2, true, W3t, b3t, H_, D_, grad, scale, shift);
        update_kernel<<<B_, D_>>>(grad, xit, tg, t, xbuf, vbuf);
    }

    // ---- output: [vT (B), xT (B*D)] ----
    writeout_kernel<<<(B_ * D_ + 255) / 256, 256>>>(vbuf, xbuf, (float*)d_out);
}

// round 3
// speedup vs baseline: 1.7595x; 1.7595x over previous
#include <cuda_runtime.h>
#include <math.h>
#include <stdint.h>

#define B_ 8192
#define D_ 256
#define H_ 266
#define T_ 20
#define NMAX 288
#define EPS 1e-5f

// ---------------- scratch (no allocation allowed) ----------------
__device__ float g_x[B_ * D_];
__device__ float g_v[B_];
__device__ float g_h1[B_ * H_];
__device__ float g_h2[B_ * H_];
__device__ float g_grad[B_ * D_];
__device__ float g_psumA[64 * NMAX];
__device__ float g_psqA[64 * NMAX];
__device__ float g_psumB[64 * NMAX];
__device__ float g_psqB[64 * NMAX];
__device__ float g_scale[NMAX];
__device__ float g_shift[NMAX];

// ---------------- helpers ----------------
__device__ __forceinline__ float tf32r(float x) {
    uint32_t o;
    asm("cvt.rna.tf32.f32 %0, %1;" : "=r"(o) : "f"(x));
    return __uint_as_float(o);
}

#define MMA8(d, av, bv)                                                        \
    asm volatile(                                                              \
        "mma.sync.aligned.m16n8k8.row.col.f32.tf32.tf32.f32 "                  \
        "{%0,%1,%2,%3},{%4,%5,%6,%7},{%8,%9},{%0,%1,%2,%3};"                   \
        : "+f"(d[0]), "+f"(d[1]), "+f"(d[2]), "+f"(d[3])                       \
        : "r"(__float_as_uint((av).x)), "r"(__float_as_uint((av).y)),          \
          "r"(__float_as_uint((av).z)), "r"(__float_as_uint((av).w)),          \
          "r"(__float_as_uint((bv).x)), "r"(__float_as_uint((bv).y)))

// SMEM float offsets
#define OFF_AB0 0
#define OFF_AB1 4096
#define OFF_WB0 8192
#define OFF_WB1 10240
#define OFF_SC 12288
#define OFF_SH 12560
#define OFF_PS 12832
#define OFF_PQ 13088
#define SMEM_FLOATS 13344
#define SMEM_BYTES (SMEM_FLOATS * 4)

// ---------------- fused GEMM + BN kernel (tf32 mma.sync) ----------------
// Y[B,N] = act(A)[B,K] @ W[N,K]^T + bias ; act = AFFINE ? relu(BN from psum_in) : id.
// STATS: also emit per-m-block column sums / sumsq of Y into psum_out/psq_out.
// grid: (64 m-blocks of 128 rows, ceil(N/64) n-blocks), 256 threads.
template <int K_ACT, int N_ACT, bool AFFINE, bool STATS>
__global__ void __launch_bounds__(256) gemm_mma(
    const float* __restrict__ A, const float* __restrict__ W,
    const float* __restrict__ bias, const float* __restrict__ bng,
    const float* __restrict__ bnb, const float* __restrict__ psum_in,
    const float* __restrict__ psq_in, float* __restrict__ Y,
    float* __restrict__ psum_out, float* __restrict__ psq_out) {
    constexpr int KCH = (K_ACT + 31) / 32;
    extern __shared__ float smf[];
    float* sc_s = smf + OFF_SC;
    float* sh_s = smf + OFF_SH;
    float* ps_s = smf + OFF_PS;  // [8 warps][32 cols]
    float* pq_s = smf + OFF_PQ;

    const int tid = threadIdx.x;
    const int w = tid >> 5, lane = tid & 31;
    const int m0 = blockIdx.x * 128;
    const int n0 = blockIdx.y * 64;

    // ---- prologue: redundant BN finalize into smem scale/shift ----
    if (AFFINE) {
        for (int n = tid; n < K_ACT; n += 256) {
            float s = 0.f, q = 0.f;
#pragma unroll 8
            for (int c = 0; c < 64; c++) {
                s += psum_in[c * NMAX + n];
                q += psq_in[c * NMAX + n];
            }
            float m = s * (1.f / B_);
            float var = q * (1.f / B_) - m * m;
            float inv = rsqrtf(var + EPS);
            float sc = bng[n] * inv;
            sc_s[n] = sc;
            sh_s[n] = bnb[n] - m * sc;
        }
        __syncthreads();
    }

    const int f4 = tid & 7, rr = tid >> 3;
    const int kloc = f4 * 4;

    // load 4 fp32 with K-stride-aware alignment, zero-fill past K
    auto ldg4 = [&](const float* p, int valid) {
        float4 v = make_float4(0.f, 0.f, 0.f, 0.f);
        if (valid >= 4) {
            if ((K_ACT & 3) == 0) {
                v = *(const float4*)p;
            } else {
                float2 u0 = *(const float2*)p, u1 = *(const float2*)(p + 2);
                v.x = u0.x; v.y = u0.y; v.z = u1.x; v.w = u1.y;
            }
        } else if (valid > 0) {
            v.x = p[0];
            if (valid > 1) v.y = p[1];
            if (valid > 2) v.z = p[2];
        }
        return v;
    };

    auto ldA = [&](int kc0, float4 r[4]) {
        const int gk = kc0 + kloc;
        const int valid = K_ACT - gk;
#pragma unroll
        for (int p = 0; p < 4; p++) {
            const int row = rr + p * 32;
            float4 v = make_float4(0.f, 0.f, 0.f, 0.f);
            if (valid > 0) v = ldg4(A + (size_t)(m0 + row) * K_ACT + gk, valid);
            if (AFFINE) {
                if (valid > 0) v.x = fmaxf(fmaf(v.x, sc_s[gk], sh_s[gk]), 0.f);
                if (valid > 1) v.y = fmaxf(fmaf(v.y, sc_s[gk + 1], sh_s[gk + 1]), 0.f);
                if (valid > 2) v.z = fmaxf(fmaf(v.z, sc_s[gk + 2], sh_s[gk + 2]), 0.f);
                if (valid > 3) v.w = fmaxf(fmaf(v.w, sc_s[gk + 3], sh_s[gk + 3]), 0.f);
            }
            v.x = tf32r(v.x); v.y = tf32r(v.y); v.z = tf32r(v.z); v.w = tf32r(v.w);
            r[p] = v;
        }
    };
    auto stA = [&](const float4 r[4], float* buf) {
        const int ks = f4 >> 1;
#pragma unroll
        for (int p = 0; p < 4; p++) {
            const int row = rr + p * 32;
            const int mt = row >> 4;
            const int reg = (f4 & 1) * 2 + ((row >> 3) & 1);
            float* q = buf + ((mt * 4 + ks) * 32 + (row & 7) * 4) * 4 + reg;
            q[0] = r[p].x; q[4] = r[p].y; q[8] = r[p].z; q[12] = r[p].w;
        }
    };
    auto ldW = [&](int kc0, float4 r[2]) {
        const int gk = kc0 + kloc;
        const int valid = K_ACT - gk;
#pragma unroll
        for (int p = 0; p < 2; p++) {
            const int n = rr + p * 32;
            float4 v = make_float4(0.f, 0.f, 0.f, 0.f);
            if (n0 + n < N_ACT && valid > 0)
                v = ldg4(W + (size_t)(n0 + n) * K_ACT + gk, valid);
            v.x = tf32r(v.x); v.y = tf32r(v.y); v.z = tf32r(v.z); v.w = tf32r(v.w);
            r[p] = v;
        }
    };
    auto stW = [&](const float4 r[2], float* buf) {
        const int ks = f4 >> 1;
        const int reg = f4 & 1;
#pragma unroll
        for (int p = 0; p < 2; p++) {
            const int n = rr + p * 32;
            const int nt = n >> 3;
            float* q = buf + ((nt * 4 + ks) * 32 + (n & 7) * 4) * 2 + reg;
            q[0] = r[p].x; q[2] = r[p].y; q[4] = r[p].z; q[6] = r[p].w;
        }
    };

    const int wm = w & 3, wn = w >> 2;
    const int mt0 = wm * 2, mt1 = wm * 2 + 1;
    float acc[2][4][4] = {};

    auto compute = [&](const float* Ab, const float* Wb) {
#pragma unroll
        for (int ks = 0; ks < 4; ks++) {
            float4 a0 = *(const float4*)(Ab + ((mt0 * 4 + ks) * 32 + lane) * 4);
            float4 a1 = *(const float4*)(Ab + ((mt1 * 4 + ks) * 32 + lane) * 4);
#pragma unroll
            for (int ni = 0; ni < 4; ni++) {
                float2 bb =
                    *(const float2*)(Wb + (((wn * 4 + ni) * 4 + ks) * 32 + lane) * 2);
                MMA8(acc[0][ni], a0, bb);
                MMA8(acc[1][ni], a1, bb);
            }
        }
    };

    // ---- pipelined mainloop ----
    {
        float4 ra[4], rw[2];
        ldA(0, ra);
        ldW(0, rw);
        stA(ra, smf + OFF_AB0);
        stW(rw, smf + OFF_WB0);
    }
    __syncthreads();
    for (int c = 0; c < KCH; c++) {
        float4 ra[4], rw[2];
        if (c + 1 < KCH) { ldA((c + 1) * 32, ra); ldW((c + 1) * 32, rw); }
        compute(smf + ((c & 1) ? OFF_AB1 : OFF_AB0),
                smf + ((c & 1) ? OFF_WB1 : OFF_WB0));
        if (c + 1 < KCH) {
            stA(ra, smf + (((c + 1) & 1) ? OFF_AB1 : OFF_AB0));
            stW(rw, smf + (((c + 1) & 1) ? OFF_WB1 : OFF_WB0));
        }
        __syncthreads();
    }

    // ---- epilogue: bias, store Y, column stats in registers ----
    const int gid = lane >> 2, t4 = lane & 3;
    const int mbase = m0 + wm * 32;
    float fA[4], fB[4], qA[4], qB[4];
#pragma unroll
    for (int ni = 0; ni < 4; ni++) {
        const int ncol = n0 + wn * 32 + ni * 8 + t4 * 2;
        float b0 = 0.f, b1 = 0.f;
        if (ncol < N_ACT) { b0 = bias[ncol]; b1 = bias[ncol + 1]; }
        float f0 = 0.f, f1 = 0.f, q0 = 0.f, q1 = 0.f;
#pragma unroll
        for (int mi = 0; mi < 2; mi++) {
            const int row = mbase + mi * 16 + gid;
            float y00 = acc[mi][ni][0] + b0;
            float y01 = acc[mi][ni][1] + b1;
            float y10 = acc[mi][ni][2] + b0;
            float y11 = acc[mi][ni][3] + b1;
            if (ncol < N_ACT) {
                *(float2*)(Y + (size_t)row * N_ACT + ncol) = make_float2(y00, y01);
                *(float2*)(Y + (size_t)(row + 8) * N_ACT + ncol) =
                    make_float2(y10, y11);
            }
            if (STATS) {
                f0 += y00 + y10;
                q0 += y00 * y00 + y10 * y10;
                f1 += y01 + y11;
                q1 += y01 * y01 + y11 * y11;
            }
        }
        fA[ni] = f0; fB[ni] = f1; qA[ni] = q0; qB[ni] = q1;
    }
    if (STATS) {
#pragma unroll
        for (int ni = 0; ni < 4; ni++) {
#pragma unroll
            for (int msk = 4; msk <= 16; msk <<= 1) {
                fA[ni] += __shfl_xor_sync(0xFFFFFFFFu, fA[ni], msk);
                fB[ni] += __shfl_xor_sync(0xFFFFFFFFu, fB[ni], msk);
                qA[ni] += __shfl_xor_sync(0xFFFFFFFFu, qA[ni], msk);
                qB[ni] += __shfl_xor_sync(0xFFFFFFFFu, qB[ni], msk);
            }
        }
        if (lane < 4) {
#pragma unroll
            for (int ni = 0; ni < 4; ni++) {
                ps_s[w * 32 + ni * 8 + t4 * 2] = fA[ni];
                ps_s[w * 32 + ni * 8 + t4 * 2 + 1] = fB[ni];
                pq_s[w * 32 + ni * 8 + t4 * 2] = qA[ni];
                pq_s[w * 32 + ni * 8 + t4 * 2 + 1] = qB[ni];
            }
        }
        __syncthreads();
        if (tid < 64) {
            const int j = tid;
            const int base = (j >> 5) * 4, jl = j & 31;
            float f = ps_s[(base + 0) * 32 + jl] + ps_s[(base + 1) * 32 + jl] +
                      ps_s[(base + 2) * 32 + jl] + ps_s[(base + 3) * 32 + jl];
            float q = pq_s[(base + 0) * 32 + jl] + pq_s[(base + 1) * 32 + jl] +
                      pq_s[(base + 2) * 32 + jl] + pq_s[(base + 3) * 32 + jl];
            const int n = n0 + j;
            if (n < NMAX) {
                psum_out[blockIdx.x * NMAX + n] = f;
                psq_out[blockIdx.x * NMAX + n] = q;
            }
        }
    }
}

// ---------------- finalize (v0 layer-2 stats -> scale/shift for v3) ----------------
__global__ void finalize_kernel(const float* __restrict__ g, const float* __restrict__ be,
                                int N, const float* __restrict__ psum,
                                const float* __restrict__ psq, float* __restrict__ scale,
                                float* __restrict__ shift) {
    int n = blockIdx.x * blockDim.x + threadIdx.x;
    if (n >= N) return;
    float s = 0.f, q = 0.f;
    for (int c = 0; c < 64; c++) { s += psum[c * NMAX + n]; q += psq[c * NMAX + n]; }
    float m = s * (1.f / B_);
    float var = q * (1.f / B_) - m * m;
    float inv = rsqrtf(var + EPS);
    float sc = g[n] * inv;
    scale[n] = sc;
    shift[n] = be[n] - m * sc;
}

// ---------------- v0 final layer (N=1) ----------------
__global__ void v3_kernel(const float* __restrict__ h2, const float* __restrict__ sc,
                          const float* __restrict__ sh, const float* __restrict__ vW3,
                          const float* __restrict__ vb3, float* __restrict__ yv) {
    int wid = threadIdx.x >> 5, lane = threadIdx.x & 31;
    int row = blockIdx.x * 8 + wid;
    const float* hr = h2 + (size_t)row * H_;
    float s = 0.f;
    for (int k = lane; k < H_; k += 32) {
        float a = fmaxf(fmaf(hr[k], sc[k], sh[k]), 0.f);
        s = fmaf(a, vW3[k], s);
    }
#pragma unroll
    for (int o = 16; o > 0; o >>= 1) s += __shfl_down_sync(0xFFFFFFFFu, s, o);
    if (lane == 0) yv[row] = s + vb3[0];
}

__global__ void v0stats_kernel(const float* __restrict__ yv, const float* __restrict__ vg3,
                               const float* __restrict__ vbe3, float* __restrict__ v) {
    __shared__ float ss[32], sq[32], bro[2];
    int tid = threadIdx.x;
    float s = 0.f, q = 0.f;
    for (int i = tid; i < B_; i += 1024) {
        float t = yv[i];
        s += t;
        q = fmaf(t, t, q);
    }
#pragma unroll
    for (int o = 16; o > 0; o >>= 1) {
        s += __shfl_down_sync(0xFFFFFFFFu, s, o);
        q += __shfl_down_sync(0xFFFFFFFFu, q, o);
    }
    if ((tid & 31) == 0) { ss[tid >> 5] = s; sq[tid >> 5] = q; }
    __syncthreads();
    if (tid == 0) {
        float S = 0.f, Q = 0.f;
        for (int i = 0; i < 32; i++) { S += ss[i]; Q += sq[i]; }
        float m = S * (1.f / B_);
        float var = Q * (1.f / B_) - m * m;
        float inv = rsqrtf(var + EPS);
        float sc = vg3[0] * inv;
        bro[0] = sc;
        bro[1] = vbe3[0] - m * sc;
    }
    __syncthreads();
    float sc = bro[0], sh = bro[1];
    for (int i = tid; i < B_; i += 1024) v[i] = fmaxf(fmaf(yv[i], sc, sh), 0.f);
}

// ---------------- per-row SDE update ----------------
__global__ void update_kernel(const float* __restrict__ grad, const float* __restrict__ xi_t,
                              const float* __restrict__ tg, int t,
                              const float* __restrict__ xsrc, float* __restrict__ xdst,
                              float* __restrict__ v) {
    const int row = blockIdx.x;
    const int d = threadIdx.x;
    const float ht = tg[t + 1] - tg[t];
    const float sh = sqrtf(ht);
    const size_t idx = (size_t)row * D_ + d;
    const float g = grad[idx];
    const float noise = sh * xi_t[idx];
    float f = g * g;
    float dt = g * noise;
#pragma unroll
    for (int o = 16; o > 0; o >>= 1) {
        f += __shfl_down_sync(0xFFFFFFFFu, f, o);
        dt += __shfl_down_sync(0xFFFFFFFFu, dt, o);
    }
    __shared__ float sf[8], sd[8];
    const int w = d >> 5;
    if ((d & 31) == 0) { sf[w] = f; sd[w] = dt; }
    __syncthreads();
    if (d == 0) {
        float F = 0.f, DT = 0.f;
#pragma unroll
        for (int i = 0; i < 8; i++) { F += sf[i]; DT += sd[i]; }
        v[row] += -F * ht + DT;
    }
    xdst[idx] = xsrc[idx] - g * ht + noise;
}

__global__ void writeout_kernel(const float* __restrict__ v, const float* __restrict__ x,
                                float* __restrict__ out) {
    int i = blockIdx.x * blockDim.x + threadIdx.x;
    if (i < B_) out[i] = v[i];
    if (i < B_ * D_) out[B_ + i] = x[i];
}

// ---------------- host orchestration ----------------
static float* sym(const void* s) {
    void* p = nullptr;
    cudaGetSymbolAddress(&p, s);
    return (float*)p;
}

extern "C" void kernel_launch(void* const* d_in, const int* in_sizes, int n_in,
                              void* d_out, int out_size) {
    const float* x    = (const float*)d_in[0];
    const float* xi   = (const float*)d_in[1];
    const float* tg   = (const float*)d_in[2];
    const float* W1   = (const float*)d_in[3];
    const float* b1   = (const float*)d_in[4];
    const float* g1   = (const float*)d_in[5];
    const float* be1  = (const float*)d_in[6];
    const float* W2   = (const float*)d_in[7];
    const float* b2   = (const float*)d_in[8];
    const float* g2   = (const float*)d_in[9];
    const float* be2  = (const float*)d_in[10];
    const float* W3   = (const float*)d_in[11];
    const float* b3   = (const float*)d_in[12];
    const float* vW1  = (const float*)d_in[13];
    const float* vb1  = (const float*)d_in[14];
    const float* vg1  = (const float*)d_in[15];
    const float* vbe1 = (const float*)d_in[16];
    const float* vW2  = (const float*)d_in[17];
    const float* vb2  = (const float*)d_in[18];
    const float* vg2  = (const float*)d_in[19];
    const float* vbe2 = (const float*)d_in[20];
    const float* vW3  = (const float*)d_in[21];
    const float* vb3  = (const float*)d_in[22];
    const float* vg3  = (const float*)d_in[23];
    const float* vbe3 = (const float*)d_in[24];

    float* xbuf = sym(g_x);
    float* vbuf = sym(g_v);
    float* h1   = sym(g_h1);
    float* h2   = sym(g_h2);
    float* grad = sym(g_grad);
    float* psA  = sym(g_psumA);
    float* pqA  = sym(g_psqA);
    float* psB  = sym(g_psumB);
    float* pqB  = sym(g_psqB);
    float* scale = sym(g_scale);
    float* shift = sym(g_shift);

    cudaFuncSetAttribute(gemm_mma<256, 266, false, true>,
                         cudaFuncAttributeMaxDynamicSharedMemorySize, SMEM_BYTES);
    cudaFuncSetAttribute(gemm_mma<266, 266, true, true>,
                         cudaFuncAttributeMaxDynamicSharedMemorySize, SMEM_BYTES);
    cudaFuncSetAttribute(gemm_mma<266, 256, true, false>,
                         cudaFuncAttributeMaxDynamicSharedMemorySize, SMEM_BYTES);

    const dim3 grid1(64, 5);  // N=266
    const dim3 grid3(64, 4);  // N=256

    // ---- v0 network ----
    gemm_mma<256, 266, false, true><<<grid1, 256, SMEM_BYTES>>>(
        x, vW1, vb1, nullptr, nullptr, nullptr, nullptr, h1, psA, pqA);
    gemm_mma<266, 266, true, true><<<grid1, 256, SMEM_BYTES>>>(
        h1, vW2, vb2, vg1, vbe1, psA, pqA, h2, psB, pqB);
    finalize_kernel<<<2, 256>>>(vg2, vbe2, H_, psB, pqB, scale, shift);
    v3_kernel<<<B_ / 8, 256>>>(h2, scale, shift, vW3, vb3, grad);
    v0stats_kernel<<<1, 1024>>>(grad, vg3, vbe3, vbuf);

    // ---- time-stepping scan ----
    for (int t = 0; t < T_; t++) {
        const float* W1t = W1 + (size_t)t * H_ * D_;
        const float* b1t = b1 + (size_t)t * H_;
        const float* g1t = g1 + (size_t)t * H_;
        const float* be1t = be1 + (size_t)t * H_;
        const float* W2t = W2 + (size_t)t * H_ * H_;
        const float* b2t = b2 + (size_t)t * H_;
        const float* g2t = g2 + (size_t)t * H_;
        const float* be2t = be2 + (size_t)t * H_;
        const float* W3t = W3 + (size_t)t * D_ * H_;
        const float* b3t = b3 + (size_t)t * D_;
        const float* xit = xi + (size_t)t * B_ * D_;
        const float* xsrc = (t == 0) ? x : xbuf;

        gemm_mma<256, 266, false, true><<<grid1, 256, SMEM_BYTES>>>(
            xsrc, W1t, b1t, nullptr, nullptr, nullptr, nullptr, h1, psA, pqA);
        gemm_mma<266, 266, true, true><<<grid1, 256, SMEM_BYTES>>>(
            h1, W2t, b2t, g1t, be1t, psA, pqA, h2, psB, pqB);
        gemm_mma<266, 256, true, false><<<grid3, 256, SMEM_BYTES>>>(
            h2, W3t, b3t, g2t, be2t, psB, pqB, grad, nullptr, nullptr);
        update_kernel<<<B_, 256>>>(grad, xit, tg, t, xsrc, xbuf, vbuf);
    }

    writeout_kernel<<<(B_ * D_ + 255) / 256, 256>>>(vbuf, xbuf, (float*)d_out);
}

// round 4
// speedup vs baseline: 1.7690x; 1.0054x over previous
#include <cuda_runtime.h>
#include <math.h>
#include <stdint.h>

#define B_ 8192
#define D_ 256
#define H_ 266
#define T_ 20
#define NMAX 288
#define EPS 1e-5f

// ---------------- scratch (no allocation allowed) ----------------
__device__ float g_x[B_ * D_];
__device__ float g_v[B_];
__device__ float g_h1[B_ * H_];
__device__ float g_h2[B_ * H_];
__device__ float g_grad[B_ * D_];
__device__ float g_psumA[64 * NMAX];
__device__ float g_psqA[64 * NMAX];
__device__ float g_psumB[64 * NMAX];
__device__ float g_psqB[64 * NMAX];
__device__ float g_scale[NMAX];
__device__ float g_shift[NMAX];

// ---------------- helpers ----------------
__device__ __forceinline__ float tf32r(float x) {
    uint32_t o;
    asm("cvt.rna.tf32.f32 %0, %1;" : "=r"(o) : "f"(x));
    return __uint_as_float(o);
}

#define MMA8(d, av, bv)                                                        \
    asm volatile(                                                              \
        "mma.sync.aligned.m16n8k8.row.col.f32.tf32.tf32.f32 "                  \
        "{%0,%1,%2,%3},{%4,%5,%6,%7},{%8,%9},{%0,%1,%2,%3};"                   \
        : "+f"(d[0]), "+f"(d[1]), "+f"(d[2]), "+f"(d[3])                       \
        : "r"(__float_as_uint((av).x)), "r"(__float_as_uint((av).y)),          \
          "r"(__float_as_uint((av).z)), "r"(__float_as_uint((av).w)),          \
          "r"(__float_as_uint((bv).x)), "r"(__float_as_uint((bv).y)))

// SMEM float offsets
#define OFF_AB0 0
#define OFF_AB1 4096
#define OFF_WB0 8192
#define OFF_WB1 10240
#define OFF_SC 12288
#define OFF_SH 12560
#define OFF_PS 12832
#define OFF_PQ 13088
#define SMEM_FLOATS 13344
#define SMEM_BYTES (SMEM_FLOATS * 4)

// ---------------- fused GEMM + BN kernel (tf32 mma.sync) ----------------
// Y[B,N] = act(A)[B,K] @ W[N,K]^T + bias ; act = AFFINE ? relu(BN from psum_in) : id.
// STATS: also emit per-m-block column sums / sumsq of Y into psum_out/psq_out.
// grid: (64 m-blocks of 128 rows, ceil(N/64) n-blocks), 256 threads.
template <int K_ACT, int N_ACT, bool AFFINE, bool STATS>
__global__ void __launch_bounds__(256) gemm_mma(
    const float* __restrict__ A, const float* __restrict__ W,
    const float* __restrict__ bias, const float* __restrict__ bng,
    const float* __restrict__ bnb, const float* __restrict__ psum_in,
    const float* __restrict__ psq_in, float* __restrict__ Y,
    float* __restrict__ psum_out, float* __restrict__ psq_out) {
    constexpr int KCH = (K_ACT + 31) / 32;
    extern __shared__ float smf[];
    float* sc_s = smf + OFF_SC;
    float* sh_s = smf + OFF_SH;
    float* ps_s = smf + OFF_PS;  // [8 warps][32 cols]
    float* pq_s = smf + OFF_PQ;

    const int tid = threadIdx.x;
    const int w = tid >> 5, lane = tid & 31;
    const int m0 = blockIdx.x * 128;
    const int n0 = blockIdx.y * 64;

    // ---- prologue: redundant BN finalize into smem scale/shift ----
    if (AFFINE) {
        for (int n = tid; n < K_ACT; n += 256) {
            float s = 0.f, q = 0.f;
#pragma unroll 8
            for (int c = 0; c < 64; c++) {
                s += psum_in[c * NMAX + n];
                q += psq_in[c * NMAX + n];
            }
            float m = s * (1.f / B_);
            float var = q * (1.f / B_) - m * m;
            float inv = rsqrtf(var + EPS);
            float sc = bng[n] * inv;
            sc_s[n] = sc;
            sh_s[n] = bnb[n] - m * sc;
        }
        __syncthreads();
    }

    const int f4 = tid & 7, rr = tid >> 3;
    const int kloc = f4 * 4;

    // load 4 fp32 with K-stride-aware alignment, zero-fill past K
    auto ldg4 = [&](const float* p, int valid) {
        float4 v = make_float4(0.f, 0.f, 0.f, 0.f);
        if (valid >= 4) {
            if ((K_ACT & 3) == 0) {
                v = *(const float4*)p;
            } else {
                float2 u0 = *(const float2*)p, u1 = *(const float2*)(p + 2);
                v.x = u0.x; v.y = u0.y; v.z = u1.x; v.w = u1.y;
            }
        } else if (valid > 0) {
            v.x = p[0];
            if (valid > 1) v.y = p[1];
            if (valid > 2) v.z = p[2];
        }
        return v;
    };

    auto ldA = [&](int kc0, float4 r[4]) {
        const int gk = kc0 + kloc;
        const int valid = K_ACT - gk;
#pragma unroll
        for (int p = 0; p < 4; p++) {
            const int row = rr + p * 32;
            float4 v = make_float4(0.f, 0.f, 0.f, 0.f);
            if (valid > 0) v = ldg4(A + (size_t)(m0 + row) * K_ACT + gk, valid);
            if (AFFINE) {
                if (valid > 0) v.x = fmaxf(fmaf(v.x, sc_s[gk], sh_s[gk]), 0.f);
                if (valid > 1) v.y = fmaxf(fmaf(v.y, sc_s[gk + 1], sh_s[gk + 1]), 0.f);
                if (valid > 2) v.z = fmaxf(fmaf(v.z, sc_s[gk + 2], sh_s[gk + 2]), 0.f);
                if (valid > 3) v.w = fmaxf(fmaf(v.w, sc_s[gk + 3], sh_s[gk + 3]), 0.f);
            }
            v.x = tf32r(v.x); v.y = tf32r(v.y); v.z = tf32r(v.z); v.w = tf32r(v.w);
            r[p] = v;
        }
    };
    auto stA = [&](const float4 r[4], float* buf) {
        const int ks = f4 >> 1;
#pragma unroll
        for (int p = 0; p < 4; p++) {
            const int row = rr + p * 32;
            const int mt = row >> 4;
            const int reg = (f4 & 1) * 2 + ((row >> 3) & 1);
            float* q = buf + ((mt * 4 + ks) * 32 + (row & 7) * 4) * 4 + reg;
            q[0] = r[p].x; q[4] = r[p].y; q[8] = r[p].z; q[12] = r[p].w;
        }
    };
    auto ldW = [&](int kc0, float4 r[2]) {
        const int gk = kc0 + kloc;
        const int valid = K_ACT - gk;
#pragma unroll
        for (int p = 0; p < 2; p++) {
            const int n = rr + p * 32;
            float4 v = make_float4(0.f, 0.f, 0.f, 0.f);
            if (n0 + n < N_ACT && valid > 0)
                v = ldg4(W + (size_t)(n0 + n) * K_ACT + gk, valid);
            v.x = tf32r(v.x); v.y = tf32r(v.y); v.z = tf32r(v.z); v.w = tf32r(v.w);
            r[p] = v;
        }
    };
    auto stW = [&](const float4 r[2], float* buf) {
        const int ks = f4 >> 1;
        const int reg = f4 & 1;
#pragma unroll
        for (int p = 0; p < 2; p++) {
            const int n = rr + p * 32;
            const int nt = n >> 3;
            float* q = buf + ((nt * 4 + ks) * 32 + (n & 7) * 4) * 2 + reg;
            q[0] = r[p].x; q[2] = r[p].y; q[4] = r[p].z; q[6] = r[p].w;
        }
    };

    const int wm = w & 3, wn = w >> 2;
    const int mt0 = wm * 2, mt1 = wm * 2 + 1;
    float acc[2][4][4] = {};

    auto compute = [&](const float* Ab, const float* Wb) {
#pragma unroll
        for (int ks = 0; ks < 4; ks++) {
            float4 a0 = *(const float4*)(Ab + ((mt0 * 4 + ks) * 32 + lane) * 4);
            float4 a1 = *(const float4*)(Ab + ((mt1 * 4 + ks) * 32 + lane) * 4);
#pragma unroll
            for (int ni = 0; ni < 4; ni++) {
                float2 bb =
                    *(const float2*)(Wb + (((wn * 4 + ni) * 4 + ks) * 32 + lane) * 2);
                MMA8(acc[0][ni], a0, bb);
                MMA8(acc[1][ni], a1, bb);
            }
        }
    };

    // ---- pipelined mainloop ----
    {
        float4 ra[4], rw[2];
        ldA(0, ra);
        ldW(0, rw);
        stA(ra, smf + OFF_AB0);
        stW(rw, smf + OFF_WB0);
    }
    __syncthreads();
    for (int c = 0; c < KCH; c++) {
        float4 ra[4], rw[2];
        if (c + 1 < KCH) { ldA((c + 1) * 32, ra); ldW((c + 1) * 32, rw); }
        compute(smf + ((c & 1) ? OFF_AB1 : OFF_AB0),
                smf + ((c & 1) ? OFF_WB1 : OFF_WB0));
        if (c + 1 < KCH) {
            stA(ra, smf + (((c + 1) & 1) ? OFF_AB1 : OFF_AB0));
            stW(rw, smf + (((c + 1) & 1) ? OFF_WB1 : OFF_WB0));
        }
        __syncthreads();
    }

    // ---- epilogue: bias, store Y, column stats in registers ----
    const int gid = lane >> 2, t4 = lane & 3;
    const int mbase = m0 + wm * 32;
    float fA[4], fB[4], qA[4], qB[4];
#pragma unroll
    for (int ni = 0; ni < 4; ni++) {
        const int ncol = n0 + wn * 32 + ni * 8 + t4 * 2;
        float b0 = 0.f, b1 = 0.f;
        if (ncol < N_ACT) { b0 = bias[ncol]; b1 = bias[ncol + 1]; }
        float f0 = 0.f, f1 = 0.f, q0 = 0.f, q1 = 0.f;
#pragma unroll
        for (int mi = 0; mi < 2; mi++) {
            const int row = mbase + mi * 16 + gid;
            float y00 = acc[mi][ni][0] + b0;
            float y01 = acc[mi][ni][1] + b1;
            float y10 = acc[mi][ni][2] + b0;
            float y11 = acc[mi][ni][3] + b1;
            if (ncol < N_ACT) {
                *(float2*)(Y + (size_t)row * N_ACT + ncol) = make_float2(y00, y01);
                *(float2*)(Y + (size_t)(row + 8) * N_ACT + ncol) =
                    make_float2(y10, y11);
            }
            if (STATS) {
                f0 += y00 + y10;
                q0 += y00 * y00 + y10 * y10;
                f1 += y01 + y11;
                q1 += y01 * y01 + y11 * y11;
            }
        }
        fA[ni] = f0; fB[ni] = f1; qA[ni] = q0; qB[ni] = q1;
    }
    if (STATS) {
#pragma unroll
        for (int ni = 0; ni < 4; ni++) {
#pragma unroll
            for (int msk = 4; msk <= 16; msk <<= 1) {
                fA[ni] += __shfl_xor_sync(0xFFFFFFFFu, fA[ni], msk);
                fB[ni] += __shfl_xor_sync(0xFFFFFFFFu, fB[ni], msk);
                qA[ni] += __shfl_xor_sync(0xFFFFFFFFu, qA[ni], msk);
                qB[ni] += __shfl_xor_sync(0xFFFFFFFFu, qB[ni], msk);
            }
        }
        if (lane < 4) {
#pragma unroll
            for (int ni = 0; ni < 4; ni++) {
                ps_s[w * 32 + ni * 8 + t4 * 2] = fA[ni];
                ps_s[w * 32 + ni * 8 + t4 * 2 + 1] = fB[ni];
                pq_s[w * 32 + ni * 8 + t4 * 2] = qA[ni];
                pq_s[w * 32 + ni * 8 + t4 * 2 + 1] = qB[ni];
            }
        }
        __syncthreads();
        if (tid < 64) {
            const int j = tid;
            const int base = (j >> 5) * 4, jl = j & 31;
            float f = ps_s[(base + 0) * 32 + jl] + ps_s[(base + 1) * 32 + jl] +
                      ps_s[(base + 2) * 32 + jl] + ps_s[(base + 3) * 32 + jl];
            float q = pq_s[(base + 0) * 32 + jl] + pq_s[(base + 1) * 32 + jl] +
                      pq_s[(base + 2) * 32 + jl] + pq_s[(base + 3) * 32 + jl];
            const int n = n0 + j;
            if (n < NMAX) {
                psum_out[blockIdx.x * NMAX + n] = f;
                psq_out[blockIdx.x * NMAX + n] = q;
            }
        }
    }
}

// ---------------- finalize (v0 layer-2 stats -> scale/shift for v3) ----------------
__global__ void finalize_kernel(const float* __restrict__ g, const float* __restrict__ be,
                                int N, const float* __restrict__ psum,
                                const float* __restrict__ psq, float* __restrict__ scale,
                                float* __restrict__ shift) {
    int n = blockIdx.x * blockDim.x + threadIdx.x;
    if (n >= N) return;
    float s = 0.f, q = 0.f;
    for (int c = 0; c < 64; c++) { s += psum[c * NMAX + n]; q += psq[c * NMAX + n]; }
    float m = s * (1.f / B_);
    float var = q * (1.f / B_) - m * m;
    float inv = rsqrtf(var + EPS);
    float sc = g[n] * inv;
    scale[n] = sc;
    shift[n] = be[n] - m * sc;
}

// ---------------- v0 final layer (N=1) ----------------
__global__ void v3_kernel(const float* __restrict__ h2, const float* __restrict__ sc,
                          const float* __restrict__ sh, const float* __restrict__ vW3,
                          const float* __restrict__ vb3, float* __restrict__ yv) {
    int wid = threadIdx.x >> 5, lane = threadIdx.x & 31;
    int row = blockIdx.x * 8 + wid;
    const float* hr = h2 + (size_t)row * H_;
    float s = 0.f;
    for (int k = lane; k < H_; k += 32) {
        float a = fmaxf(fmaf(hr[k], sc[k], sh[k]), 0.f);
        s = fmaf(a, vW3[k], s);
    }
#pragma unroll
    for (int o = 16; o > 0; o >>= 1) s += __shfl_down_sync(0xFFFFFFFFu, s, o);
    if (lane == 0) yv[row] = s + vb3[0];
}

__global__ void v0stats_kernel(const float* __restrict__ yv, const float* __restrict__ vg3,
                               const float* __restrict__ vbe3, float* __restrict__ v) {
    __shared__ float ss[32], sq[32], bro[2];
    int tid = threadIdx.x;
    float s = 0.f, q = 0.f;
    for (int i = tid; i < B_; i += 1024) {
        float t = yv[i];
        s += t;
        q = fmaf(t, t, q);
    }
#pragma unroll
    for (int o = 16; o > 0; o >>= 1) {
        s += __shfl_down_sync(0xFFFFFFFFu, s, o);
        q += __shfl_down_sync(0xFFFFFFFFu, q, o);
    }
    if ((tid & 31) == 0) { ss[tid >> 5] = s; sq[tid >> 5] = q; }
    __syncthreads();
    if (tid == 0) {
        float S = 0.f, Q = 0.f;
        for (int i = 0; i < 32; i++) { S += ss[i]; Q += sq[i]; }
        float m = S * (1.f / B_);
        float var = Q * (1.f / B_) - m * m;
        float inv = rsqrtf(var + EPS);
        float sc = vg3[0] * inv;
        bro[0] = sc;
        bro[1] = vbe3[0] - m * sc;
    }
    __syncthreads();
    float sc = bro[0], sh = bro[1];
    for (int i = tid; i < B_; i += 1024) v[i] = fmaxf(fmaf(yv[i], sc, sh), 0.f);
}

// ---------------- per-row SDE update ----------------
__global__ void update_kernel(const float* __restrict__ grad, const float* __restrict__ xi_t,
                              const float* __restrict__ tg, int t,
                              const float* __restrict__ xsrc, float* __restrict__ xdst,
                              float* __restrict__ v) {
    const int row = blockIdx.x;
    const int d = threadIdx.x;
    const float ht = tg[t + 1] - tg[t];
    const float sh = sqrtf(ht);
    const size_t idx = (size_t)row * D_ + d;
    const float g = grad[idx];
    const float noise = sh * xi_t[idx];
    float f = g * g;
    float dt = g * noise;
#pragma unroll
    for (int o = 16; o > 0; o >>= 1) {
        f += __shfl_down_sync(0xFFFFFFFFu, f, o);
        dt += __shfl_down_sync(0xFFFFFFFFu, dt, o);
    }
    __shared__ float sf[8], sd[8];
    const int w = d >> 5;
    if ((d & 31) == 0) { sf[w] = f; sd[w] = dt; }
    __syncthreads();
    if (d == 0) {
        float F = 0.f, DT = 0.f;
#pragma unroll
        for (int i = 0; i < 8; i++) { F += sf[i]; DT += sd[i]; }
        v[row] += -F * ht + DT;
    }
    xdst[idx] = xsrc[idx] - g * ht + noise;
}

__global__ void writeout_kernel(const float* __restrict__ v, const float* __restrict__ x,
                                float* __restrict__ out) {
    int i = blockIdx.x * blockDim.x + threadIdx.x;
    if (i < B_) out[i] = v[i];
    if (i < B_ * D_) out[B_ + i] = x[i];
}

// ---------------- host orchestration ----------------
static float* sym(const void* s) {
    void* p = nullptr;
    cudaGetSymbolAddress(&p, s);
    return (float*)p;
}

extern "C" void kernel_launch(void* const* d_in, const int* in_sizes, int n_in,
                              void* d_out, int out_size) {
    const float* x    = (const float*)d_in[0];
    const float* xi   = (const float*)d_in[1];
    const float* tg   = (const float*)d_in[2];
    const float* W1   = (const float*)d_in[3];
    const float* b1   = (const float*)d_in[4];
    const float* g1   = (const float*)d_in[5];
    const float* be1  = (const float*)d_in[6];
    const float* W2   = (const float*)d_in[7];
    const float* b2   = (const float*)d_in[8];
    const float* g2   = (const float*)d_in[9];
    const float* be2  = (const float*)d_in[10];
    const float* W3   = (const float*)d_in[11];
    const float* b3   = (const float*)d_in[12];
    const float* vW1  = (const float*)d_in[13];
    const float* vb1  = (const float*)d_in[14];
    const float* vg1  = (const float*)d_in[15];
    const float* vbe1 = (const float*)d_in[16];
    const float* vW2  = (const float*)d_in[17];
    const float* vb2  = (const float*)d_in[18];
    const float* vg2  = (const float*)d_in[19];
    const float* vbe2 = (const float*)d_in[20];
    const float* vW3  = (const float*)d_in[21];
    const float* vb3  = (const float*)d_in[22];
    const float* vg3  = (const float*)d_in[23];
    const float* vbe3 = (const float*)d_in[24];

    float* xbuf = sym(g_x);
    float* vbuf = sym(g_v);
    float* h1   = sym(g_h1);
    float* h2   = sym(g_h2);
    float* grad = sym(g_grad);
    float* psA  = sym(g_psumA);
    float* pqA  = sym(g_psqA);
    float* psB  = sym(g_psumB);
    float* pqB  = sym(g_psqB);
    float* scale = sym(g_scale);
    float* shift = sym(g_shift);

    cudaFuncSetAttribute(gemm_mma<256, 266, false, true>,
                         cudaFuncAttributeMaxDynamicSharedMemorySize, SMEM_BYTES);
    cudaFuncSetAttribute(gemm_mma<266, 266, true, true>,
                         cudaFuncAttributeMaxDynamicSharedMemorySize, SMEM_BYTES);
    cudaFuncSetAttribute(gemm_mma<266, 256, true, false>,
                         cudaFuncAttributeMaxDynamicSharedMemorySize, SMEM_BYTES);

    const dim3 grid1(64, 5);  // N=266
    const dim3 grid3(64, 4);  // N=256

    // ---- v0 network ----
    gemm_mma<256, 266, false, true><<<grid1, 256, SMEM_BYTES>>>(
        x, vW1, vb1, nullptr, nullptr, nullptr, nullptr, h1, psA, pqA);
    gemm_mma<266, 266, true, true><<<grid1, 256, SMEM_BYTES>>>(
        h1, vW2, vb2, vg1, vbe1, psA, pqA, h2, psB, pqB);
    finalize_kernel<<<2, 256>>>(vg2, vbe2, H_, psB, pqB, scale, shift);
    v3_kernel<<<B_ / 8, 256>>>(h2, scale, shift, vW3, vb3, grad);
    v0stats_kernel<<<1, 1024>>>(grad, vg3, vbe3, vbuf);

    // ---- time-stepping scan ----
    for (int t = 0; t < T_; t++) {
        const float* W1t = W1 + (size_t)t * H_ * D_;
        const float* b1t = b1 + (size_t)t * H_;
        const float* g1t = g1 + (size_t)t * H_;
        const float* be1t = be1 + (size_t)t * H_;
        const float* W2t = W2 + (size_t)t * H_ * H_;
        const float* b2t = b2 + (size_t)t * H_;
        const float* g2t = g2 + (size_t)t * H_;
        const float* be2t = be2 + (size_t)t * H_;
        const float* W3t = W3 + (size_t)t * D_ * H_;
        const float* b3t = b3 + (size_t)t * D_;
        const float* xit = xi + (size_t)t * B_ * D_;
        const float* xsrc = (t == 0) ? x : xbuf;

        gemm_mma<256, 266, false, true><<<grid1, 256, SMEM_BYTES>>>(
            xsrc, W1t, b1t, nullptr, nullptr, nullptr, nullptr, h1, psA, pqA);
        gemm_mma<266, 266, true, true><<<grid1, 256, SMEM_BYTES>>>(
            h1, W2t, b2t, g1t, be1t, psA, pqA, h2, psB, pqB);
        gemm_mma<266, 256, true, false><<<grid3, 256, SMEM_BYTES>>>(
            h2, W3t, b3t, g2t, be2t, psB, pqB, grad, nullptr, nullptr);
        update_kernel<<<B_, 256>>>(grad, xit, tg, t, xsrc, xbuf, vbuf);
    }

    writeout_kernel<<<(B_ * D_ + 255) / 256, 256>>>(vbuf, xbuf, (float*)d_out);
}

// round 5
// speedup vs baseline: 2.9363x; 1.6599x over previous
#include <cuda_runtime.h>
#include <math.h>
#include <stdint.h>

#define B_ 8192
#define D_ 256
#define H_ 266
#define T_ 20
#define NB 128
#define EPS 1e-5f

// ---------------- persistent state (no allocation allowed) ----------------
__device__ float g_x[B_ * D_];
__device__ float g_h1[B_ * H_];
__device__ float g_h2[B_ * H_];
__device__ float g_psA[288 * NB];
__device__ float g_pqA[288 * NB];
__device__ float g_psB[288 * NB];
__device__ float g_pqB[288 * NB];
__device__ unsigned g_cnt;
__device__ unsigned g_epoch;

// ---------------- smem layout (float offsets) ----------------
// stage: A 64x36 (2304) + B 288x36 (10368) = 12672 floats; 3 stages
#define STG 12672
#define OFF_SC 38016
#define OFF_SH 38304
#define OFF_RED 38592  // 1280 floats scratch (stats ps/pq, update red, yv)
#define OFF_VS 39872   // 64 floats: per-row v (persists whole kernel)
#define OFF_BC 39936   // 8 floats broadcast
#define SMEM_FLOATS 39944
#define SMEM_BYTES (SMEM_FLOATS * 4)

// ---------------- low-level helpers ----------------
__device__ __forceinline__ uint32_t smem_u32(const void* p) {
    uint32_t a;
    asm("{ .reg .u64 t; cvta.to.shared.u64 t, %1; cvt.u32.u64 %0, t; }" : "=r"(a) : "l"(p));
    return a;
}
__device__ __forceinline__ uint32_t tf32r(float x) {
    uint32_t o;
    asm("cvt.rna.tf32.f32 %0, %1;" : "=r"(o) : "f"(x));
    return o;
}
__device__ __forceinline__ void cpa8(uint32_t dst, const void* src, int sz) {
    asm volatile("cp.async.ca.shared.global [%0], [%1], 8, %2;" :: "r"(dst), "l"(src),
                 "r"(sz));
}
#define MMAU(d, a, b0, b1)                                                    \
    asm volatile(                                                             \
        "mma.sync.aligned.m16n8k8.row.col.f32.tf32.tf32.f32 "                 \
        "{%0,%1,%2,%3},{%4,%5,%6,%7},{%8,%9},{%0,%1,%2,%3};"                  \
        : "+f"(d[0]), "+f"(d[1]), "+f"(d[2]), "+f"(d[3])                      \
        : "r"(a[0]), "r"(a[1]), "r"(a[2]), "r"(a[3]), "r"(b0), "r"(b1))

// epoch-based global barrier: safe across graph replays (epoch monotonic,
// count self-resets to 0 each barrier).
__device__ __forceinline__ void gbar() {
    __syncthreads();
    if (threadIdx.x == 0) {
        unsigned e0 = *(volatile unsigned*)&g_epoch;
        __threadfence();
        unsigned old = atomicAdd(&g_cnt, 1u);
        if (old == NB - 1) {
            *(volatile unsigned*)&g_cnt = 0u;
            __threadfence();
            atomicAdd(&g_epoch, 1u);
        } else {
            while (*(volatile unsigned*)&g_epoch == e0) { __nanosleep(64); }
        }
        __threadfence();
    }
    __syncthreads();
}

// ---------------- BN finalize into smem scale/shift (per-CTA redundant) ----------------
__device__ __forceinline__ void finalize_sm(const float* __restrict__ psin,
                                            const float* __restrict__ pqin,
                                            const float* __restrict__ bng,
                                            const float* __restrict__ bnb, int K_ACT,
                                            float* sm, int tid) {
    float* scS = sm + OFF_SC;
    float* shS = sm + OFF_SH;
    for (int n = tid; n < 288; n += 256) {
        if (n < K_ACT) {
            const float4* pp = (const float4*)(psin + n * NB);
            const float4* qq = (const float4*)(pqin + n * NB);
            float s = 0.f, q = 0.f;
#pragma unroll 8
            for (int b = 0; b < NB / 4; b++) {
                float4 u = pp[b];
                s += (u.x + u.y) + (u.z + u.w);
                float4 v2 = qq[b];
                q += (v2.x + v2.y) + (v2.z + v2.w);
            }
            float m = s * (1.f / B_);
            float var = q * (1.f / B_) - m * m;
            float inv = rsqrtf(var + EPS);
            float sc = bng[n] * inv;
            scS[n] = sc;
            shS[n] = bnb[n] - m * sc;
        } else {
            scS[n] = 0.f;  // padded k-columns contribute exactly 0 after affine
            shS[n] = 0.f;
        }
    }
    __syncthreads();
}

// ---------------- GEMM mainloop: acc[2][NT][4] += act(A)[64,K] @ W[.,K]^T ----------------
// warp grid 2(m) x 4(n); warp tile 32 x NT*8; cp.async 3-stage pipeline.
template <int K_ACT, int NT, bool AFFINE>
__device__ __forceinline__ void do_gemm(const float* __restrict__ Ag,
                                        const float* __restrict__ Wg, int N_ACT,
                                        float* sm, int bid, int tid,
                                        float acc[2][NT][4]) {
    constexpr int NC = (K_ACT + 31) / 32;
    const int lane = tid & 31, w = tid >> 5, wm = w >> 2, wn = w & 3;
    const int gm0 = bid * 64;
    const float* scS = sm + OFF_SC;
    const float* shS = sm + OFF_SH;

    auto issue = [&](int ch) {
        float* As = sm + (ch % 3) * STG;
        float* Bs = As + 2304;
#pragma unroll
        for (int l = 0; l < 4; l++) {
            int i = tid + l * 256;
            int row = i >> 4, kk = (i & 15) * 2, gk = ch * 32 + kk;
            int sz = (K_ACT - gk) * 4;
            sz = sz < 0 ? 0 : (sz > 8 ? 8 : sz);
            const float* src = Ag + (size_t)(gm0 + row) * K_ACT + (sz > 0 ? gk : 0);
            cpa8(smem_u32(As + row * 36 + kk), src, sz);
        }
#pragma unroll
        for (int l = 0; l < 18; l++) {
            int i = tid + l * 256;
            int n = i >> 4, kk = (i & 15) * 2, gk = ch * 32 + kk;
            int sz = (K_ACT - gk) * 4;
            sz = sz < 0 ? 0 : (sz > 8 ? 8 : sz);
            if (n >= N_ACT) sz = 0;
            const float* src = Wg + (sz > 0 ? ((size_t)n * K_ACT + gk) : 0);
            cpa8(smem_u32(Bs + n * 36 + kk), src, sz);
        }
        asm volatile("cp.async.commit_group;" ::: "memory");
    };

    issue(0);
    issue(1);
    for (int ch = 0; ch < NC; ch++) {
        if (ch + 2 < NC) {
            issue(ch + 2);
            asm volatile("cp.async.wait_group 2;" ::: "memory");
        } else if (ch + 1 < NC) {
            asm volatile("cp.async.wait_group 1;" ::: "memory");
        } else {
            asm volatile("cp.async.wait_group 0;" ::: "memory");
        }
        __syncthreads();
        const float* As = sm + (ch % 3) * STG;
        const float* Bs = As + 2304;
#pragma unroll
        for (int s = 0; s < 4; s++) {
            const int kc = s * 8 + (lane & 3);
            float sc0 = 0.f, sh0 = 0.f, sc4 = 0.f, sh4 = 0.f;
            if (AFFINE) {
                int kg = ch * 32 + kc;
                sc0 = scS[kg]; sh0 = shS[kg];
                sc4 = scS[kg + 4]; sh4 = shS[kg + 4];
            }
            uint32_t a[2][4];
#pragma unroll
            for (int mt = 0; mt < 2; mt++) {
                const int r = wm * 32 + mt * 16 + (lane >> 2);
                float x0 = As[r * 36 + kc];
                float x1 = As[(r + 8) * 36 + kc];
                float x2 = As[r * 36 + kc + 4];
                float x3 = As[(r + 8) * 36 + kc + 4];
                if (AFFINE) {
                    x0 = fmaxf(fmaf(x0, sc0, sh0), 0.f);
                    x1 = fmaxf(fmaf(x1, sc0, sh0), 0.f);
                    x2 = fmaxf(fmaf(x2, sc4, sh4), 0.f);
                    x3 = fmaxf(fmaf(x3, sc4, sh4), 0.f);
                }
                a[mt][0] = tf32r(x0); a[mt][1] = tf32r(x1);
                a[mt][2] = tf32r(x2); a[mt][3] = tf32r(x3);
            }
#pragma unroll
            for (int nt = 0; nt < NT; nt++) {
                const int n = wn * (NT * 8) + nt * 8 + (lane >> 2);
                uint32_t b0 = __float_as_uint(Bs[n * 36 + kc]);
                uint32_t b1 = __float_as_uint(Bs[n * 36 + kc + 4]);
                MMAU(acc[0][nt], a[0], b0, b1);
                MMAU(acc[1][nt], a[1], b0, b1);
            }
        }
        __syncthreads();
    }
}

// ---------------- epilogue: bias, store Y, column stats (transposed partials) ----------------
__device__ __forceinline__ void epi_stats(float acc[2][9][4], const float* __restrict__ bias,
                                          float* __restrict__ Yg, int N_ACT,
                                          float* __restrict__ pso, float* __restrict__ pqo,
                                          float* sm, int bid, int tid) {
    const int lane = tid & 31, w = tid >> 5, wm = w >> 2, wn = w & 3;
    float* ps = sm + OFF_RED;
    float* pq = sm + OFF_RED + 640;
#pragma unroll
    for (int nt = 0; nt < 9; nt++) {
        const int c0 = wn * 72 + nt * 8 + 2 * (lane & 3);
        float b0 = 0.f, b1 = 0.f;
        if (c0 < N_ACT) { b0 = bias[c0]; b1 = bias[c0 + 1]; }
        float s0 = 0.f, s1 = 0.f, q0 = 0.f, q1 = 0.f;
#pragma unroll
        for (int mt = 0; mt < 2; mt++) {
            const int rbase = bid * 64 + wm * 32 + mt * 16 + (lane >> 2);
#pragma unroll
            for (int rs = 0; rs < 2; rs++) {
                float y0 = acc[mt][nt][rs * 2 + 0] + b0;
                float y1 = acc[mt][nt][rs * 2 + 1] + b1;
                const int row = rbase + rs * 8;
                if (c0 < N_ACT)
                    *(float2*)(Yg + (size_t)row * N_ACT + c0) = make_float2(y0, y1);
                s0 += y0; s1 += y1;
                q0 += y0 * y0; q1 += y1 * y1;
            }
        }
#pragma unroll
        for (int m = 4; m <= 16; m <<= 1) {
            s0 += __shfl_xor_sync(~0u, s0, m);
            s1 += __shfl_xor_sync(~0u, s1, m);
            q0 += __shfl_xor_sync(~0u, q0, m);
            q1 += __shfl_xor_sync(~0u, q1, m);
        }
        if (lane < 4) {
            ps[w * 80 + nt * 8 + 2 * lane] = s0;
            ps[w * 80 + nt * 8 + 2 * lane + 1] = s1;
            pq[w * 80 + nt * 8 + 2 * lane] = q0;
            pq[w * 80 + nt * 8 + 2 * lane + 1] = q1;
        }
    }
    __syncthreads();
    for (int n = tid; n < 288; n += 256) {
        int wn2 = n / 72, cw = n - wn2 * 72;
        float s = ps[wn2 * 80 + cw] + ps[(4 + wn2) * 80 + cw];
        float q = pq[wn2 * 80 + cw] + pq[(4 + wn2) * 80 + cw];
        pso[n * NB + bid] = s;
        pqo[n * NB + bid] = q;
    }
    __syncthreads();
}

// ---------------- L3 epilogue fused with SDE update ----------------
__device__ __forceinline__ void epi_update(float acc[2][8][4], const float* __restrict__ b3,
                                           const float* __restrict__ xi_t,
                                           const float* __restrict__ xsrc,
                                           float* __restrict__ xdst, float ht, float* sm,
                                           int bid, int tid) {
    const int lane = tid & 31, w = tid >> 5, wm = w >> 2, wn = w & 3;
    const float sq = sqrtf(ht);
    float fa[2][2] = {}, da[2][2] = {};
#pragma unroll
    for (int nt = 0; nt < 8; nt++) {
        const int c0 = wn * 64 + nt * 8 + 2 * (lane & 3);
        const float b0 = b3[c0], b1 = b3[c0 + 1];
#pragma unroll
        for (int mt = 0; mt < 2; mt++) {
#pragma unroll
            for (int rs = 0; rs < 2; rs++) {
                const int row = bid * 64 + wm * 32 + mt * 16 + (lane >> 2) + rs * 8;
                float gg0 = acc[mt][nt][rs * 2 + 0] + b0;
                float gg1 = acc[mt][nt][rs * 2 + 1] + b1;
                float2 xi2 = *(const float2*)(xi_t + (size_t)row * 256 + c0);
                float2 xs2 = *(const float2*)(xsrc + (size_t)row * 256 + c0);
                float n0 = sq * xi2.x, n1 = sq * xi2.y;
                fa[mt][rs] += gg0 * gg0 + gg1 * gg1;
                da[mt][rs] += gg0 * n0 + gg1 * n1;
                *(float2*)(xdst + (size_t)row * 256 + c0) =
                    make_float2(xs2.x - gg0 * ht + n0, xs2.y - gg1 * ht + n1);
            }
        }
    }
#pragma unroll
    for (int m = 1; m <= 2; m <<= 1) {
#pragma unroll
        for (int mt = 0; mt < 2; mt++)
#pragma unroll
            for (int rs = 0; rs < 2; rs++) {
                fa[mt][rs] += __shfl_xor_sync(~0u, fa[mt][rs], m);
                da[mt][rs] += __shfl_xor_sync(~0u, da[mt][rs], m);
            }
    }
    float* rf = sm + OFF_RED;
    float* rd = sm + OFF_RED + 256;
    if ((lane & 3) == 0) {
#pragma unroll
        for (int mt = 0; mt < 2; mt++)
#pragma unroll
            for (int rs = 0; rs < 2; rs++) {
                int rl = wm * 32 + mt * 16 + (lane >> 2) + rs * 8;
                rf[wn * 64 + rl] = fa[mt][rs];
                rd[wn * 64 + rl] = da[mt][rs];
            }
    }
    __syncthreads();
    if (tid < 64) {
        float F = rf[tid] + rf[64 + tid] + rf[128 + tid] + rf[192 + tid];
        float Dt = rd[tid] + rd[64 + tid] + rd[128 + tid] + rd[192 + tid];
        sm[OFF_VS + tid] += -F * ht + Dt;
    }
    __syncthreads();
}

// ---------------- v0 tail: N=1 layer + its BN stats/final ----------------
__device__ __forceinline__ void v3_part(const float* __restrict__ h2,
                                        const float* __restrict__ vW3,
                                        const float* __restrict__ vb3, float* sm, int bid,
                                        int tid) {
    const int lane = tid & 31, w = tid >> 5;
    const float* scS = sm + OFF_SC;
    const float* shS = sm + OFF_SH;
    float* yv = sm + OFF_RED;  // 64 rows
    for (int i = 0; i < 8; i++) {
        int row = w * 8 + i;
        size_t base = (size_t)(bid * 64 + row) * H_;
        float s = 0.f;
        for (int k = lane; k < H_; k += 32) {
            float a2 = fmaxf(fmaf(h2[base + k], scS[k], shS[k]), 0.f);
            s = fmaf(a2, vW3[k], s);
        }
#pragma unroll
        for (int m = 16; m > 0; m >>= 1) s += __shfl_xor_sync(~0u, s, m);
        if (lane == 0) yv[row] = s + vb3[0];
    }
    __syncthreads();
    if (tid == 0) {
        float s = 0.f, q = 0.f;
        for (int i = 0; i < 64; i++) {
            float t = yv[i];
            s += t;
            q = fmaf(t, t, q);
        }
        g_psA[bid] = s;  // transposed layout, col 0
        g_pqA[bid] = q;
    }
    __syncthreads();
}

__device__ __forceinline__ void v0_final(const float* __restrict__ vg3,
                                         const float* __restrict__ vbe3, float* sm,
                                         int tid) {
    float* yv = sm + OFF_RED;
    float* bc = sm + OFF_BC;
    if (tid == 0) {
        float s = 0.f, q = 0.f;
        for (int b = 0; b < NB; b++) { s += g_psA[b]; q += g_pqA[b]; }
        float m = s * (1.f / B_);
        float var = q * (1.f / B_) - m * m;
        float inv = rsqrtf(var + EPS);
        float sc = vg3[0] * inv;
        bc[0] = sc;
        bc[1] = vbe3[0] - m * sc;
    }
    __syncthreads();
    if (tid < 64) sm[OFF_VS + tid] = fmaxf(fmaf(yv[tid], bc[0], bc[1]), 0.f);
    __syncthreads();
}

// ---------------- the persistent mega-kernel ----------------
__global__ void __launch_bounds__(256) mega(
    const float* __restrict__ x, const float* __restrict__ xi,
    const float* __restrict__ tg, const float* __restrict__ W1,
    const float* __restrict__ b1, const float* __restrict__ g1,
    const float* __restrict__ be1, const float* __restrict__ W2,
    const float* __restrict__ b2, const float* __restrict__ g2,
    const float* __restrict__ be2, const float* __restrict__ W3,
    const float* __restrict__ b3, const float* __restrict__ vW1,
    const float* __restrict__ vb1, const float* __restrict__ vg1,
    const float* __restrict__ vbe1, const float* __restrict__ vW2,
    const float* __restrict__ vb2, const float* __restrict__ vg2,
    const float* __restrict__ vbe2, const float* __restrict__ vW3,
    const float* __restrict__ vb3, const float* __restrict__ vg3,
    const float* __restrict__ vbe3, float* __restrict__ out) {
    extern __shared__ float sm[];
    const int bid = blockIdx.x, tid = threadIdx.x;

    // ---- v0 network ----
    {
        float acc[2][9][4] = {};
        do_gemm<256, 9, false>(x, vW1, 266, sm, bid, tid, acc);
        epi_stats(acc, vb1, g_h1, 266, g_psA, g_pqA, sm, bid, tid);
    }
    gbar();
    finalize_sm(g_psA, g_pqA, vg1, vbe1, 266, sm, tid);
    {
        float acc[2][9][4] = {};
        do_gemm<266, 9, true>(g_h1, vW2, 266, sm, bid, tid, acc);
        epi_stats(acc, vb2, g_h2, 266, g_psB, g_pqB, sm, bid, tid);
    }
    gbar();
    finalize_sm(g_psB, g_pqB, vg2, vbe2, 266, sm, tid);
    v3_part(g_h2, vW3, vb3, sm, bid, tid);
    gbar();
    v0_final(vg3, vbe3, sm, tid);

    // ---- time-stepping scan ----
    for (int t = 0; t < T_; t++) {
        const float* xsrc = (t == 0) ? x : g_x;
        const float* W1t = W1 + (size_t)t * H_ * D_;
        const float* b1t = b1 + (size_t)t * H_;
        const float* g1t = g1 + (size_t)t * H_;
        const float* be1t = be1 + (size_t)t * H_;
        const float* W2t = W2 + (size_t)t * H_ * H_;
        const float* b2t = b2 + (size_t)t * H_;
        const float* g2t = g2 + (size_t)t * H_;
        const float* be2t = be2 + (size_t)t * H_;
        const float* W3t = W3 + (size_t)t * D_ * H_;
        const float* b3t = b3 + (size_t)t * D_;
        const float* xit = xi + (size_t)t * B_ * D_;

        {
            float acc[2][9][4] = {};
            do_gemm<256, 9, false>(xsrc, W1t, 266, sm, bid, tid, acc);
            epi_stats(acc, b1t, g_h1, 266, g_psA, g_pqA, sm, bid, tid);
        }
        gbar();
        finalize_sm(g_psA, g_pqA, g1t, be1t, 266, sm, tid);
        {
            float acc[2][9][4] = {};
            do_gemm<266, 9, true>(g_h1, W2t, 266, sm, bid, tid, acc);
            epi_stats(acc, b2t, g_h2, 266, g_psB, g_pqB, sm, bid, tid);
        }
        gbar();
        finalize_sm(g_psB, g_pqB, g2t, be2t, 266, sm, tid);
        {
            float acc[2][8][4] = {};
            do_gemm<266, 8, true>(g_h2, W3t, 256, sm, bid, tid, acc);
            float ht = tg[t + 1] - tg[t];
            float* xdst = (t == T_ - 1) ? (out + B_) : g_x;
            epi_update(acc, b3t, xit, xsrc, xdst, ht, sm, bid, tid);
        }
        // no barrier needed: all consumed state (x, h1, h2, v) is CTA-local;
        // psA/psB of step t were fully read before the barriers above.
    }

    // ---- output v ----
    if (tid < 64) out[bid * 64 + tid] = sm[OFF_VS + tid];
}

// ---------------- host ----------------
extern "C" void kernel_launch(void* const* d_in, const int* in_sizes, int n_in,
                              void* d_out, int out_size) {
    const float* x    = (const float*)d_in[0];
    const float* xi   = (const float*)d_in[1];
    const float* tg   = (const float*)d_in[2];
    const float* W1   = (const float*)d_in[3];
    const float* b1   = (const float*)d_in[4];
    const float* g1   = (const float*)d_in[5];
    const float* be1  = (const float*)d_in[6];
    const float* W2   = (const float*)d_in[7];
    const float* b2   = (const float*)d_in[8];
    const float* g2   = (const float*)d_in[9];
    const float* be2  = (const float*)d_in[10];
    const float* W3   = (const float*)d_in[11];
    const float* b3   = (const float*)d_in[12];
    const float* vW1  = (const float*)d_in[13];
    const float* vb1  = (const float*)d_in[14];
    const float* vg1  = (const float*)d_in[15];
    const float* vbe1 = (const float*)d_in[16];
    const float* vW2  = (const float*)d_in[17];
    const float* vb2  = (const float*)d_in[18];
    const float* vg2  = (const float*)d_in[19];
    const float* vbe2 = (const float*)d_in[20];
    const float* vW3  = (const float*)d_in[21];
    const float* vb3  = (const float*)d_in[22];
    const float* vg3  = (const float*)d_in[23];
    const float* vbe3 = (const float*)d_in[24];

    cudaFuncSetAttribute(mega, cudaFuncAttributeMaxDynamicSharedMemorySize, SMEM_BYTES);
    mega<<<NB, 256, SMEM_BYTES>>>(x, xi, tg, W1, b1, g1, be1, W2, b2, g2, be2, W3, b3,
                                  vW1, vb1, vg1, vbe1, vW2, vb2, vg2, vbe2, vW3, vb3,
                                  vg3, vbe3, (float*)d_out);
}